// round 16
// baseline (speedup 1.0000x reference)
#include <cuda_runtime.h>
#include <cuda_bf16.h>
#include <math_constants.h>
#include <cstdint>

// Problem constants
#define IN_F   1024
#define OUT_F  2048
#define BATCH  8192
#define LR     0.02f
#define ANTI   0.4f
#define PREC   1e-30f

// ---------------- scratch (no allocations allowed) ----------------
__device__ float          g_ds[(size_t)OUT_F * IN_F];
__device__ int            g_idx0[BATCH];
__device__ int            g_idx1[BATCH];
__device__ unsigned int   g_nc;
__device__ int            g_cnt[OUT_F];        // match counts
__device__ int            g_rowptr[OUT_F + 1];
__device__ int            g_blist[2 * BATCH];
__device__ float          g_clist[2 * BATCH];
// bf16 split matrices
__device__ __nv_bfloat16  g_xhi[(size_t)BATCH * IN_F];
__device__ __nv_bfloat16  g_xlo[(size_t)BATCH * IN_F];
__device__ __nv_bfloat16  g_whi[(size_t)OUT_F * IN_F];
__device__ __nv_bfloat16  g_wlo[(size_t)OUT_F * IN_F];

// ================= helpers =================
__device__ __forceinline__ uint32_t smem_u32(const void* p) {
    uint32_t a;
    asm("{ .reg .u64 t; cvta.to.shared.u64 t, %1; cvt.u32.u64 %0, t; }" : "=r"(a) : "l"(p));
    return a;
}
__device__ __forceinline__ void cp16(uint32_t sm, const void* g) {
    asm volatile("cp.async.cg.shared.global [%0], [%1], 16;" :: "r"(sm), "l"(g) : "memory");
}
__device__ __forceinline__ void cp_commit() {
    asm volatile("cp.async.commit_group;" ::: "memory");
}
template <int N>
__device__ __forceinline__ void cp_wait() {
    asm volatile("cp.async.wait_group %0;" :: "n"(N) : "memory");
}
__device__ __forceinline__ void mma_bf16(float* d, const uint32_t* a, const uint32_t* b) {
    asm volatile(
        "mma.sync.aligned.m16n8k16.row.col.f32.bf16.bf16.f32 "
        "{%0,%1,%2,%3}, {%4,%5,%6,%7}, {%8,%9}, {%0,%1,%2,%3};"
        : "+f"(d[0]), "+f"(d[1]), "+f"(d[2]), "+f"(d[3])
        : "r"(a[0]), "r"(a[1]), "r"(a[2]), "r"(a[3]), "r"(b[0]), "r"(b[1]));
}
__device__ __forceinline__ void ldsm4(uint32_t& r0, uint32_t& r1, uint32_t& r2, uint32_t& r3,
                                      uint32_t addr) {
    asm volatile("ldmatrix.sync.aligned.m8n8.x4.shared.b16 {%0,%1,%2,%3}, [%4];"
                 : "=r"(r0), "=r"(r1), "=r"(r2), "=r"(r3) : "r"(addr));
}

// ================= fused split kernel: {x,w} -> (bf16 hi, bf16 lo) =========
__global__ __launch_bounds__(256)
void split_bf16_fused(const float4* __restrict__ x4, const float4* __restrict__ w4,
                      uint2* __restrict__ xhi, uint2* __restrict__ xlo,
                      uint2* __restrict__ whi, uint2* __restrict__ wlo,
                      int n4x, int n4tot) {
    int i = blockIdx.x * blockDim.x + threadIdx.x;
    if (i == 0) g_nc = __float_as_uint(PREC);   // reset for this launch
    if (i < OUT_F) g_cnt[i] = 0;                // zero match counters
    if (i >= n4tot) return;
    const float4* src; uint2 *hi, *lo; int idx;
    if (i < n4x) { src = x4; hi = xhi; lo = xlo; idx = i; }
    else         { src = w4; hi = whi; lo = wlo; idx = i - n4x; }
    float4 v = src[idx];
    __nv_bfloat16 h0 = __float2bfloat16(v.x);
    __nv_bfloat16 h1 = __float2bfloat16(v.y);
    __nv_bfloat16 h2 = __float2bfloat16(v.z);
    __nv_bfloat16 h3 = __float2bfloat16(v.w);
    __nv_bfloat16 l0 = __float2bfloat16(v.x - __bfloat162float(h0));
    __nv_bfloat16 l1 = __float2bfloat16(v.y - __bfloat162float(h1));
    __nv_bfloat16 l2 = __float2bfloat16(v.z - __bfloat162float(h2));
    __nv_bfloat16 l3 = __float2bfloat16(v.w - __bfloat162float(h3));
    __nv_bfloat162 hp0 = __halves2bfloat162(h0, h1);
    __nv_bfloat162 hp1 = __halves2bfloat162(h2, h3);
    __nv_bfloat162 lp0 = __halves2bfloat162(l0, l1);
    __nv_bfloat162 lp1 = __halves2bfloat162(l2, l3);
    uint2 hv, lv;
    hv.x = *reinterpret_cast<uint32_t*>(&hp0); hv.y = *reinterpret_cast<uint32_t*>(&hp1);
    lv.x = *reinterpret_cast<uint32_t*>(&lp0); lv.y = *reinterpret_cast<uint32_t*>(&lp1);
    hi[idx] = hv; lo[idx] = lv;
}

// ================= bf16 mma.sync GEMM (round-12 proven config) ============
// 3-product split folded into K. 128x128 CTA tiles, 8 warps (64x32 warp
// tiles), 2 CTAs/SM, 3-stage cp.async pipeline, 1 barrier per chunk.
#define BM_T 128
#define BN_T 128
#define ROWB 144u
#define STAGE_B ((BM_T + BN_T) * ROWB)   // 256*144 = 36864
#define NSTAGEG 3
#define NCHUNKG 48
#define SMEM_GEMM (NSTAGEG * STAGE_B)    // 110592 (x2 CTAs = 221184)

__global__ __launch_bounds__(256, 2)
void gemm_bf16_kernel(const __nv_bfloat16* __restrict__ Xhi,
                      const __nv_bfloat16* __restrict__ Xlo,
                      const __nv_bfloat16* __restrict__ Whi,
                      const __nv_bfloat16* __restrict__ Wlo,
                      float* __restrict__ C) {
    extern __shared__ char smem[];
    const uint32_t sb = smem_u32(smem);
    const int tid  = threadIdx.x;
    const int wid  = tid >> 5;
    const int lane = tid & 31;
    const int gr   = lane >> 2;
    const int tig  = lane & 3;
    const int wm   = wid & 1;      // 2 warp rows (64 each)
    const int wn   = wid >> 1;     // 4 warp cols (32 each)
    const int m0 = blockIdx.y * BM_T;
    const int n0 = blockIdx.x * BN_T;

    const uint32_t aoff = (uint32_t)(wm * 64 + (lane & 15)) * ROWB + (uint32_t)(lane >> 4) * 16;
    const uint32_t boff = (uint32_t)(wn * 32 + ((lane >> 4) * 8) + (lane & 7)) * ROWB
                        + (uint32_t)((lane >> 3) & 1) * 16;

    auto issue_chunk = [&](int s) {
        const int region = s >> 4;
        const int kb = (s & 15) * 128;
        const __nv_bfloat16* Asrc = (region == 1) ? Xlo : Xhi;
        const __nv_bfloat16* Bsrc = (region == 2) ? Wlo : Whi;
        const uint32_t base = sb + (uint32_t)(s % NSTAGEG) * STAGE_B;
        #pragma unroll
        for (int c = 0; c < 8; c++) {
            int idx = tid + c * 256;
            int row = idx >> 3, g = idx & 7;
            const char* gp;
            if (row < BM_T)
                gp = (const char*)Asrc + (size_t)(m0 + row) * (IN_F * 2) + kb + g * 16;
            else
                gp = (const char*)Bsrc + (size_t)(n0 + row - BM_T) * (IN_F * 2) + kb + g * 16;
            cp16(base + row * ROWB + g * 16, gp);
        }
        cp_commit();
    };

    float acc[4][4][4];
    #pragma unroll
    for (int i = 0; i < 4; i++)
        #pragma unroll
        for (int j = 0; j < 4; j++)
            #pragma unroll
            for (int r = 0; r < 4; r++) acc[i][j][r] = 0.f;

    issue_chunk(0);
    issue_chunk(1);

    for (int s = 0; s < NCHUNKG; s++) {
        if (s == NCHUNKG - 1) cp_wait<0>(); else cp_wait<1>();
        __syncthreads();
        // stage (s+2)%3 was fully consumed before the barrier above
        if (s + 2 < NCHUNKG) issue_chunk(s + 2);

        const uint32_t base = sb + (uint32_t)(s % NSTAGEG) * STAGE_B;
        const uint32_t aB = base + aoff;
        const uint32_t bB = base + BM_T * ROWB + boff;

        #pragma unroll
        for (int ks = 0; ks < 4; ks++) {
            const uint32_t k0b = (uint32_t)ks * 32;
            uint32_t a[4][4], b[4][2];
            #pragma unroll
            for (int i = 0; i < 4; i++)
                ldsm4(a[i][0], a[i][1], a[i][2], a[i][3],
                      aB + (uint32_t)i * (16 * ROWB) + k0b);
            ldsm4(b[0][0], b[0][1], b[1][0], b[1][1], bB + k0b);
            ldsm4(b[2][0], b[2][1], b[3][0], b[3][1], bB + 16 * ROWB + k0b);
            #pragma unroll
            for (int i = 0; i < 4; i++)
                #pragma unroll
                for (int j = 0; j < 4; j++)
                    mma_bf16(acc[i][j], a[i], b[j]);
        }
    }

    #pragma unroll
    for (int i = 0; i < 4; i++) {
        int r0 = m0 + wm * 64 + i * 16 + gr;
        #pragma unroll
        for (int j = 0; j < 4; j++) {
            int cc = n0 + wn * 32 + j * 8 + 2 * tig;
            *reinterpret_cast<float2*>(C + (size_t)r0 * OUT_F + cc) =
                make_float2(acc[i][j][0], acc[i][j][1]);
            *reinterpret_cast<float2*>(C + (size_t)(r0 + 8) * OUT_F + cc) =
                make_float2(acc[i][j][2], acc[i][j][3]);
        }
    }
}

// ---------------- Top-2 per batch row (warp per row, 2-way ILP) -----------
__device__ __forceinline__ void merge_top2(float& av1, int& ai1, float& av2, int& ai2,
                                           float bv1, int bi1, float bv2, int bi2) {
    if (bv1 > av1 || (bv1 == av1 && bi1 < ai1)) {
        float nv2; int ni2;
        if (av1 > bv2 || (av1 == bv2 && ai1 < bi2)) { nv2 = av1; ni2 = ai1; }
        else                                         { nv2 = bv2; ni2 = bi2; }
        av1 = bv1; ai1 = bi1; av2 = nv2; ai2 = ni2;
    } else {
        if (bv1 > av2 || (bv1 == av2 && bi1 < ai2)) { av2 = bv1; ai2 = bi1; }
    }
}

__global__ __launch_bounds__(256)
void top2_kernel(const float* __restrict__ y) {
    const int warp = threadIdx.x >> 5;
    const int lane = threadIdx.x & 31;
    const int row  = blockIdx.x * 8 + warp;

    const float4* r4 = reinterpret_cast<const float4*>(y + (size_t)row * OUT_F);
    // two independent trackers to halve the dependent compare chain
    float p1 = -CUDART_INF_F, p2 = -CUDART_INF_F;
    int   pi1 = 0x7fffffff,   pi2 = 0x7fffffff;
    float q1 = -CUDART_INF_F, q2 = -CUDART_INF_F;
    int   qi1 = 0x7fffffff,   qi2 = 0x7fffffff;

    auto updP = [&](float v, int j) {
        if (v > p1) { p2 = p1; pi2 = pi1; p1 = v; pi1 = j; }
        else if (v > p2) { p2 = v; pi2 = j; }
    };
    auto updQ = [&](float v, int j) {
        if (v > q1) { q2 = q1; qi2 = qi1; q1 = v; qi1 = j; }
        else if (v > q2) { q2 = v; qi2 = j; }
    };
    #pragma unroll
    for (int k = 0; k < 16; k++) {
        int j4 = lane + 32 * k;
        float4 v = r4[j4];
        int jb = 4 * j4;
        updP(v.x, jb); updQ(v.y, jb + 1); updP(v.z, jb + 2); updQ(v.w, jb + 3);
    }
    // merge Q into P (exact: both use (value, lower-index) order)
    merge_top2(p1, pi1, p2, pi2, q1, qi1, q2, qi2);

    #pragma unroll
    for (int off = 16; off > 0; off >>= 1) {
        float ov1 = __shfl_xor_sync(0xffffffffu, p1, off);
        int   oi1 = __shfl_xor_sync(0xffffffffu, pi1, off);
        float ov2 = __shfl_xor_sync(0xffffffffu, p2, off);
        int   oi2 = __shfl_xor_sync(0xffffffffu, pi2, off);
        merge_top2(p1, pi1, p2, pi2, ov1, oi1, ov2, oi2);
    }
    if (lane == 0) {
        g_idx0[row] = pi1; g_idx1[row] = pi2;
        atomicAdd(&g_cnt[pi1], 1);
        atomicAdd(&g_cnt[pi2], 1);
    }
}

// ---------------- fused scan + fill (single block) -------------------------
__global__ __launch_bounds__(1024)
void scan_fill_kernel() {
    __shared__ int scur[OUT_F];             // segment cursors (smem atomics)
    __shared__ int wsum[32];
    const int t = threadIdx.x;              // 0..1023, pair (2t, 2t+1)

    int v0 = g_cnt[2 * t], v1 = g_cnt[2 * t + 1];
    int s = v0 + v1;
    int incl = s;
    #pragma unroll
    for (int off = 1; off < 32; off <<= 1) {
        int n = __shfl_up_sync(0xffffffffu, incl, off);
        if ((t & 31) >= off) incl += n;
    }
    if ((t & 31) == 31) wsum[t >> 5] = incl;
    __syncthreads();
    if (t < 32) {
        int w = wsum[t];
        int wincl = w;
        #pragma unroll
        for (int off = 1; off < 32; off <<= 1) {
            int n = __shfl_up_sync(0xffffffffu, wincl, off);
            if (t >= off) wincl += n;
        }
        wsum[t] = wincl - w;                // exclusive warp base
    }
    __syncthreads();
    int base = wsum[t >> 5] + (incl - s);   // exclusive prefix of this pair
    g_rowptr[2 * t]     = base;
    g_rowptr[2 * t + 1] = base + v0;
    scur[2 * t]         = base;
    scur[2 * t + 1]     = base + v0;
    if (t == 1023) g_rowptr[OUT_F] = base + s;
    __syncthreads();

    // fill CSR lists: 8192 batches over 1024 threads
    #pragma unroll
    for (int r = 0; r < BATCH / 1024; r++) {
        int b = t + r * 1024;
        int o0 = g_idx0[b];
        int pos0 = atomicAdd(&scur[o0], 1);
        g_blist[pos0] = b; g_clist[pos0] = 1.0f;
        int o1 = g_idx1[b];
        int pos1 = atomicAdd(&scur[o1], 1);
        g_blist[pos1] = b; g_clist[pos1] = -ANTI;
    }
}

// ---------------- ds = yl@x - xx*W, and nc = max|ds| (CSR) ----------------
__global__ __launch_bounds__(256)
void update_kernel(const float* __restrict__ x, const float* __restrict__ w,
                   const float* __restrict__ y, int OUT) {
    const int o   = blockIdx.x;
    const int tid = threadIdx.x;
    const int start = g_rowptr[o];
    const int end   = g_rowptr[o + 1];

    __shared__ float sxx;
    if (tid == 0) sxx = 0.f;
    __syncthreads();

    float xxloc = 0.f;
    for (int m = start + tid; m < end; m += 256)
        xxloc += g_clist[m] * y[(size_t)g_blist[m] * OUT_F + o];
    #pragma unroll
    for (int off = 16; off > 0; off >>= 1)
        xxloc += __shfl_xor_sync(0xffffffffu, xxloc, off);
    if ((tid & 31) == 0 && xxloc != 0.f) atomicAdd(&sxx, xxloc);
    __syncthreads();
    const float xx = sxx;

    float4 acc = make_float4(0.f, 0.f, 0.f, 0.f);
    for (int m = start; m < end; m++) {
        const float c = g_clist[m];
        const float4 xv = reinterpret_cast<const float4*>(
            x + (size_t)g_blist[m] * IN_F)[tid];
        acc.x = fmaf(c, xv.x, acc.x);
        acc.y = fmaf(c, xv.y, acc.y);
        acc.z = fmaf(c, xv.z, acc.z);
        acc.w = fmaf(c, xv.w, acc.w);
    }

    const float4 wv = reinterpret_cast<const float4*>(w + (size_t)o * IN_F)[tid];
    float4 d;
    d.x = acc.x - xx * wv.x;
    d.y = acc.y - xx * wv.y;
    d.z = acc.z - xx * wv.z;
    d.w = acc.w - xx * wv.w;
    reinterpret_cast<float4*>(g_ds + (size_t)o * IN_F)[tid] = d;

    float lmax = fmaxf(fmaxf(fabsf(d.x), fabsf(d.y)), fmaxf(fabsf(d.z), fabsf(d.w)));
    #pragma unroll
    for (int off = 16; off > 0; off >>= 1)
        lmax = fmaxf(lmax, __shfl_xor_sync(0xffffffffu, lmax, off));
    __shared__ float smax[8];
    if ((tid & 31) == 0) smax[tid >> 5] = lmax;
    __syncthreads();
    if (tid == 0) {
        float m = smax[0];
        #pragma unroll
        for (int k = 1; k < 8; k++) m = fmaxf(m, smax[k]);
        atomicMax(&g_nc, __float_as_uint(m));
    }
}

// ---------------- new_w = w + LR * ds / nc ----------------
__global__ __launch_bounds__(256)
void finalize_kernel(const float4* __restrict__ w4, float4* __restrict__ neww4, int n4) {
    const float inv = LR / __uint_as_float(g_nc);
    int i = blockIdx.x * blockDim.x + threadIdx.x;
    if (i < n4) {
        const float4* ds4 = reinterpret_cast<const float4*>(g_ds);
        float4 d = ds4[i];
        float4 v = w4[i];
        v.x = fmaf(d.x, inv, v.x);
        v.y = fmaf(d.y, inv, v.y);
        v.z = fmaf(d.z, inv, v.z);
        v.w = fmaf(d.w, inv, v.w);
        neww4[i] = v;
    }
}

// ---------------- launch ----------------
extern "C" void kernel_launch(void* const* d_in, const int* in_sizes, int n_in,
                              void* d_out, int out_size) {
    const float* x = (const float*)d_in[0];
    const float* w = (const float*)d_in[1];
    if (n_in >= 2 && in_sizes[0] == OUT_F * IN_F && in_sizes[1] == BATCH * IN_F) {
        w = (const float*)d_in[0];
        x = (const float*)d_in[1];
    }

    float* y_out = (float*)d_out;                       // [BATCH, OUT_F]
    float* w_out = y_out + (size_t)BATCH * OUT_F;       // [OUT_F, IN_F]

    __nv_bfloat16 *xhi, *xlo, *whi, *wlo;
    cudaGetSymbolAddress((void**)&xhi, g_xhi);
    cudaGetSymbolAddress((void**)&xlo, g_xlo);
    cudaGetSymbolAddress((void**)&whi, g_whi);
    cudaGetSymbolAddress((void**)&wlo, g_wlo);

    // 0) fused bf16 splits (+ nc/counter reset)
    {
        int n4x = BATCH * IN_F / 4;
        int n4t = n4x + OUT_F * IN_F / 4;
        split_bf16_fused<<<(n4t + 255) / 256, 256>>>(
            (const float4*)x, (const float4*)w,
            (uint2*)xhi, (uint2*)xlo, (uint2*)whi, (uint2*)wlo, n4x, n4t);
    }
    // 1) y = x @ W^T via bf16 mma.sync (round-12 config)
    {
        cudaFuncSetAttribute(gemm_bf16_kernel,
                             cudaFuncAttributeMaxDynamicSharedMemorySize, SMEM_GEMM);
        dim3 grid(OUT_F / BN_T, BATCH / BM_T);
        gemm_bf16_kernel<<<grid, 256, SMEM_GEMM>>>(xhi, xlo, whi, wlo, y_out);
    }
    // 2) top-2 per batch row + match counting
    top2_kernel<<<BATCH / 8, 256>>>(y_out);
    // 3) fused CSR build (scan + fill, one block)
    scan_fill_kernel<<<1, 1024>>>();
    // 4) ds + global max (CSR-driven)
    update_kernel<<<OUT_F, 256>>>(x, w, y_out, OUT_F);
    // 5) finalize
    {
        int n4 = OUT_F * IN_F / 4;
        finalize_kernel<<<(n4 + 255) / 256, 256>>>((const float4*)w, (float4*)w_out, n4);
    }
}

// round 17
// speedup vs baseline: 1.0429x; 1.0429x over previous
#include <cuda_runtime.h>
#include <cuda_bf16.h>
#include <math_constants.h>
#include <cstdint>

// Problem constants
#define IN_F   1024
#define OUT_F  2048
#define BATCH  8192
#define LR     0.02f
#define ANTI   0.4f
#define PREC   1e-30f

// ---------------- scratch (no allocations allowed) ----------------
__device__ float          g_ds[(size_t)OUT_F * IN_F];
__device__ int            g_idx0[BATCH];
__device__ int            g_idx1[BATCH];
__device__ unsigned int   g_nc;
__device__ int            g_cnt[OUT_F];        // counts, then segment cursors
__device__ int            g_rowptr[OUT_F + 1];
__device__ int            g_blist[2 * BATCH];
__device__ float          g_clist[2 * BATCH];
// bf16 split matrices
__device__ __nv_bfloat16  g_xhi[(size_t)BATCH * IN_F];
__device__ __nv_bfloat16  g_xlo[(size_t)BATCH * IN_F];
__device__ __nv_bfloat16  g_whi[(size_t)OUT_F * IN_F];
__device__ __nv_bfloat16  g_wlo[(size_t)OUT_F * IN_F];

// ================= helpers =================
__device__ __forceinline__ uint32_t smem_u32(const void* p) {
    uint32_t a;
    asm("{ .reg .u64 t; cvta.to.shared.u64 t, %1; cvt.u32.u64 %0, t; }" : "=r"(a) : "l"(p));
    return a;
}
__device__ __forceinline__ void cp16(uint32_t sm, const void* g) {
    asm volatile("cp.async.cg.shared.global [%0], [%1], 16;" :: "r"(sm), "l"(g) : "memory");
}
__device__ __forceinline__ void cp_commit() {
    asm volatile("cp.async.commit_group;" ::: "memory");
}
template <int N>
__device__ __forceinline__ void cp_wait() {
    asm volatile("cp.async.wait_group %0;" :: "n"(N) : "memory");
}
__device__ __forceinline__ void mma_bf16(float* d, const uint32_t* a, const uint32_t* b) {
    asm volatile(
        "mma.sync.aligned.m16n8k16.row.col.f32.bf16.bf16.f32 "
        "{%0,%1,%2,%3}, {%4,%5,%6,%7}, {%8,%9}, {%0,%1,%2,%3};"
        : "+f"(d[0]), "+f"(d[1]), "+f"(d[2]), "+f"(d[3])
        : "r"(a[0]), "r"(a[1]), "r"(a[2]), "r"(a[3]), "r"(b[0]), "r"(b[1]));
}
__device__ __forceinline__ void ldsm4(uint32_t& r0, uint32_t& r1, uint32_t& r2, uint32_t& r3,
                                      uint32_t addr) {
    asm volatile("ldmatrix.sync.aligned.m8n8.x4.shared.b16 {%0,%1,%2,%3}, [%4];"
                 : "=r"(r0), "=r"(r1), "=r"(r2), "=r"(r3) : "r"(addr));
}

// ================= fused split kernel: {x,w} -> (bf16 hi, bf16 lo) =========
__global__ __launch_bounds__(256)
void split_bf16_fused(const float4* __restrict__ x4, const float4* __restrict__ w4,
                      uint2* __restrict__ xhi, uint2* __restrict__ xlo,
                      uint2* __restrict__ whi, uint2* __restrict__ wlo,
                      int n4x, int n4tot) {
    int i = blockIdx.x * blockDim.x + threadIdx.x;
    if (i == 0) g_nc = __float_as_uint(PREC);   // reset for this launch
    if (i < OUT_F) g_cnt[i] = 0;                // zero match counters
    if (i >= n4tot) return;
    const float4* src; uint2 *hi, *lo; int idx;
    if (i < n4x) { src = x4; hi = xhi; lo = xlo; idx = i; }
    else         { src = w4; hi = whi; lo = wlo; idx = i - n4x; }
    float4 v = src[idx];
    __nv_bfloat16 h0 = __float2bfloat16(v.x);
    __nv_bfloat16 h1 = __float2bfloat16(v.y);
    __nv_bfloat16 h2 = __float2bfloat16(v.z);
    __nv_bfloat16 h3 = __float2bfloat16(v.w);
    __nv_bfloat16 l0 = __float2bfloat16(v.x - __bfloat162float(h0));
    __nv_bfloat16 l1 = __float2bfloat16(v.y - __bfloat162float(h1));
    __nv_bfloat16 l2 = __float2bfloat16(v.z - __bfloat162float(h2));
    __nv_bfloat16 l3 = __float2bfloat16(v.w - __bfloat162float(h3));
    __nv_bfloat162 hp0 = __halves2bfloat162(h0, h1);
    __nv_bfloat162 hp1 = __halves2bfloat162(h2, h3);
    __nv_bfloat162 lp0 = __halves2bfloat162(l0, l1);
    __nv_bfloat162 lp1 = __halves2bfloat162(l2, l3);
    uint2 hv, lv;
    hv.x = *reinterpret_cast<uint32_t*>(&hp0); hv.y = *reinterpret_cast<uint32_t*>(&hp1);
    lv.x = *reinterpret_cast<uint32_t*>(&lp0); lv.y = *reinterpret_cast<uint32_t*>(&lp1);
    hi[idx] = hv; lo[idx] = lv;
}

// ================= bf16 mma.sync GEMM (round-12 proven config) ============
// 3-product split folded into K. 128x128 CTA tiles, 8 warps (64x32 warp
// tiles), 2 CTAs/SM, 3-stage cp.async pipeline, 1 barrier per chunk.
#define BM_T 128
#define BN_T 128
#define ROWB 144u
#define STAGE_B ((BM_T + BN_T) * ROWB)   // 256*144 = 36864
#define NSTAGEG 3
#define NCHUNKG 48
#define SMEM_GEMM (NSTAGEG * STAGE_B)    // 110592 (x2 CTAs = 221184)

__global__ __launch_bounds__(256, 2)
void gemm_bf16_kernel(const __nv_bfloat16* __restrict__ Xhi,
                      const __nv_bfloat16* __restrict__ Xlo,
                      const __nv_bfloat16* __restrict__ Whi,
                      const __nv_bfloat16* __restrict__ Wlo,
                      float* __restrict__ C) {
    extern __shared__ char smem[];
    const uint32_t sb = smem_u32(smem);
    const int tid  = threadIdx.x;
    const int wid  = tid >> 5;
    const int lane = tid & 31;
    const int gr   = lane >> 2;
    const int tig  = lane & 3;
    const int wm   = wid & 1;      // 2 warp rows (64 each)
    const int wn   = wid >> 1;     // 4 warp cols (32 each)
    const int m0 = blockIdx.y * BM_T;
    const int n0 = blockIdx.x * BN_T;

    const uint32_t aoff = (uint32_t)(wm * 64 + (lane & 15)) * ROWB + (uint32_t)(lane >> 4) * 16;
    const uint32_t boff = (uint32_t)(wn * 32 + ((lane >> 4) * 8) + (lane & 7)) * ROWB
                        + (uint32_t)((lane >> 3) & 1) * 16;

    auto issue_chunk = [&](int s) {
        const int region = s >> 4;
        const int kb = (s & 15) * 128;
        const __nv_bfloat16* Asrc = (region == 1) ? Xlo : Xhi;
        const __nv_bfloat16* Bsrc = (region == 2) ? Wlo : Whi;
        const uint32_t base = sb + (uint32_t)(s % NSTAGEG) * STAGE_B;
        #pragma unroll
        for (int c = 0; c < 8; c++) {
            int idx = tid + c * 256;
            int row = idx >> 3, g = idx & 7;
            const char* gp;
            if (row < BM_T)
                gp = (const char*)Asrc + (size_t)(m0 + row) * (IN_F * 2) + kb + g * 16;
            else
                gp = (const char*)Bsrc + (size_t)(n0 + row - BM_T) * (IN_F * 2) + kb + g * 16;
            cp16(base + row * ROWB + g * 16, gp);
        }
        cp_commit();
    };

    float acc[4][4][4];
    #pragma unroll
    for (int i = 0; i < 4; i++)
        #pragma unroll
        for (int j = 0; j < 4; j++)
            #pragma unroll
            for (int r = 0; r < 4; r++) acc[i][j][r] = 0.f;

    issue_chunk(0);
    issue_chunk(1);

    for (int s = 0; s < NCHUNKG; s++) {
        if (s == NCHUNKG - 1) cp_wait<0>(); else cp_wait<1>();
        __syncthreads();
        // stage (s+2)%3 was fully consumed before the barrier above
        if (s + 2 < NCHUNKG) issue_chunk(s + 2);

        const uint32_t base = sb + (uint32_t)(s % NSTAGEG) * STAGE_B;
        const uint32_t aB = base + aoff;
        const uint32_t bB = base + BM_T * ROWB + boff;

        #pragma unroll
        for (int ks = 0; ks < 4; ks++) {
            const uint32_t k0b = (uint32_t)ks * 32;
            uint32_t a[4][4], b[4][2];
            #pragma unroll
            for (int i = 0; i < 4; i++)
                ldsm4(a[i][0], a[i][1], a[i][2], a[i][3],
                      aB + (uint32_t)i * (16 * ROWB) + k0b);
            ldsm4(b[0][0], b[0][1], b[1][0], b[1][1], bB + k0b);
            ldsm4(b[2][0], b[2][1], b[3][0], b[3][1], bB + 16 * ROWB + k0b);
            #pragma unroll
            for (int i = 0; i < 4; i++)
                #pragma unroll
                for (int j = 0; j < 4; j++)
                    mma_bf16(acc[i][j], a[i], b[j]);
        }
    }

    #pragma unroll
    for (int i = 0; i < 4; i++) {
        int r0 = m0 + wm * 64 + i * 16 + gr;
        #pragma unroll
        for (int j = 0; j < 4; j++) {
            int cc = n0 + wn * 32 + j * 8 + 2 * tig;
            *reinterpret_cast<float2*>(C + (size_t)r0 * OUT_F + cc) =
                make_float2(acc[i][j][0], acc[i][j][1]);
            *reinterpret_cast<float2*>(C + (size_t)(r0 + 8) * OUT_F + cc) =
                make_float2(acc[i][j][2], acc[i][j][3]);
        }
    }
}

// ---------------- Top-2 per batch row (warp per row, 2-way ILP) -----------
__device__ __forceinline__ void merge_top2(float& av1, int& ai1, float& av2, int& ai2,
                                           float bv1, int bi1, float bv2, int bi2) {
    if (bv1 > av1 || (bv1 == av1 && bi1 < ai1)) {
        float nv2; int ni2;
        if (av1 > bv2 || (av1 == bv2 && ai1 < bi2)) { nv2 = av1; ni2 = ai1; }
        else                                         { nv2 = bv2; ni2 = bi2; }
        av1 = bv1; ai1 = bi1; av2 = nv2; ai2 = ni2;
    } else {
        if (bv1 > av2 || (bv1 == av2 && bi1 < ai2)) { av2 = bv1; ai2 = bi1; }
    }
}

__global__ __launch_bounds__(256)
void top2_kernel(const float* __restrict__ y) {
    const int warp = threadIdx.x >> 5;
    const int lane = threadIdx.x & 31;
    const int row  = blockIdx.x * 8 + warp;

    const float4* r4 = reinterpret_cast<const float4*>(y + (size_t)row * OUT_F);
    // two independent trackers to halve the dependent compare chain
    float p1 = -CUDART_INF_F, p2 = -CUDART_INF_F;
    int   pi1 = 0x7fffffff,   pi2 = 0x7fffffff;
    float q1 = -CUDART_INF_F, q2 = -CUDART_INF_F;
    int   qi1 = 0x7fffffff,   qi2 = 0x7fffffff;

    auto updP = [&](float v, int j) {
        if (v > p1) { p2 = p1; pi2 = pi1; p1 = v; pi1 = j; }
        else if (v > p2) { p2 = v; pi2 = j; }
    };
    auto updQ = [&](float v, int j) {
        if (v > q1) { q2 = q1; qi2 = qi1; q1 = v; qi1 = j; }
        else if (v > q2) { q2 = v; qi2 = j; }
    };
    #pragma unroll
    for (int k = 0; k < 16; k++) {
        int j4 = lane + 32 * k;
        float4 v = r4[j4];
        int jb = 4 * j4;
        updP(v.x, jb); updQ(v.y, jb + 1); updP(v.z, jb + 2); updQ(v.w, jb + 3);
    }
    // merge Q into P (exact: both use (value, lower-index) order)
    merge_top2(p1, pi1, p2, pi2, q1, qi1, q2, qi2);

    #pragma unroll
    for (int off = 16; off > 0; off >>= 1) {
        float ov1 = __shfl_xor_sync(0xffffffffu, p1, off);
        int   oi1 = __shfl_xor_sync(0xffffffffu, pi1, off);
        float ov2 = __shfl_xor_sync(0xffffffffu, p2, off);
        int   oi2 = __shfl_xor_sync(0xffffffffu, pi2, off);
        merge_top2(p1, pi1, p2, pi2, ov1, oi1, ov2, oi2);
    }
    if (lane == 0) {
        g_idx0[row] = pi1; g_idx1[row] = pi2;
        atomicAdd(&g_cnt[pi1], 1);
        atomicAdd(&g_cnt[pi2], 1);
    }
}

// ---------------- exclusive scan of g_cnt -> g_rowptr (shfl-based) --------
__global__ __launch_bounds__(1024)
void scan_kernel() {
    const int t = threadIdx.x;              // 0..1023, pair (2t, 2t+1)
    int v0 = g_cnt[2 * t], v1 = g_cnt[2 * t + 1];
    int s = v0 + v1;
    int incl = s;
    #pragma unroll
    for (int off = 1; off < 32; off <<= 1) {
        int n = __shfl_up_sync(0xffffffffu, incl, off);
        if ((t & 31) >= off) incl += n;
    }
    __shared__ int wsum[32];
    if ((t & 31) == 31) wsum[t >> 5] = incl;
    __syncthreads();
    if (t < 32) {
        int w = wsum[t];
        int wincl = w;
        #pragma unroll
        for (int off = 1; off < 32; off <<= 1) {
            int n = __shfl_up_sync(0xffffffffu, wincl, off);
            if (t >= off) wincl += n;
        }
        wsum[t] = wincl - w;                // exclusive warp base
    }
    __syncthreads();
    int base = wsum[t >> 5] + (incl - s);   // exclusive prefix of this pair
    g_rowptr[2 * t]     = base;
    g_rowptr[2 * t + 1] = base + v0;
    g_cnt[2 * t]        = base;             // segment cursors for fill
    g_cnt[2 * t + 1]    = base + v0;
    if (t == 1023) g_rowptr[OUT_F] = base + s;
}

// ---------------- fill CSR lists ------------------------------------------
__global__ __launch_bounds__(256)
void fill_kernel() {
    int b = blockIdx.x * blockDim.x + threadIdx.x;
    if (b >= BATCH) return;
    int o0 = g_idx0[b];
    int p0 = atomicAdd(&g_cnt[o0], 1);
    g_blist[p0] = b; g_clist[p0] = 1.0f;
    int o1 = g_idx1[b];
    int p1 = atomicAdd(&g_cnt[o1], 1);
    g_blist[p1] = b; g_clist[p1] = -ANTI;
}

// ---------------- ds = yl@x - xx*W, and nc = max|ds| (CSR) ----------------
__global__ __launch_bounds__(256)
void update_kernel(const float* __restrict__ x, const float* __restrict__ w,
                   const float* __restrict__ y, int OUT) {
    const int o   = blockIdx.x;
    const int tid = threadIdx.x;
    const int start = g_rowptr[o];
    const int end   = g_rowptr[o + 1];

    __shared__ float sxx;
    if (tid == 0) sxx = 0.f;
    __syncthreads();

    float xxloc = 0.f;
    for (int m = start + tid; m < end; m += 256)
        xxloc += g_clist[m] * y[(size_t)g_blist[m] * OUT_F + o];
    #pragma unroll
    for (int off = 16; off > 0; off >>= 1)
        xxloc += __shfl_xor_sync(0xffffffffu, xxloc, off);
    if ((tid & 31) == 0 && xxloc != 0.f) atomicAdd(&sxx, xxloc);
    __syncthreads();
    const float xx = sxx;

    float4 acc = make_float4(0.f, 0.f, 0.f, 0.f);
    for (int m = start; m < end; m++) {
        const float c = g_clist[m];
        const float4 xv = reinterpret_cast<const float4*>(
            x + (size_t)g_blist[m] * IN_F)[tid];
        acc.x = fmaf(c, xv.x, acc.x);
        acc.y = fmaf(c, xv.y, acc.y);
        acc.z = fmaf(c, xv.z, acc.z);
        acc.w = fmaf(c, xv.w, acc.w);
    }

    const float4 wv = reinterpret_cast<const float4*>(w + (size_t)o * IN_F)[tid];
    float4 d;
    d.x = acc.x - xx * wv.x;
    d.y = acc.y - xx * wv.y;
    d.z = acc.z - xx * wv.z;
    d.w = acc.w - xx * wv.w;
    reinterpret_cast<float4*>(g_ds + (size_t)o * IN_F)[tid] = d;

    float lmax = fmaxf(fmaxf(fabsf(d.x), fabsf(d.y)), fmaxf(fabsf(d.z), fabsf(d.w)));
    #pragma unroll
    for (int off = 16; off > 0; off >>= 1)
        lmax = fmaxf(lmax, __shfl_xor_sync(0xffffffffu, lmax, off));
    __shared__ float smax[8];
    if ((tid & 31) == 0) smax[tid >> 5] = lmax;
    __syncthreads();
    if (tid == 0) {
        float m = smax[0];
        #pragma unroll
        for (int k = 1; k < 8; k++) m = fmaxf(m, smax[k]);
        atomicMax(&g_nc, __float_as_uint(m));
    }
}

// ---------------- new_w = w + LR * ds / nc ----------------
__global__ __launch_bounds__(256)
void finalize_kernel(const float4* __restrict__ w4, float4* __restrict__ neww4, int n4) {
    const float inv = LR / __uint_as_float(g_nc);
    int i = blockIdx.x * blockDim.x + threadIdx.x;
    if (i < n4) {
        const float4* ds4 = reinterpret_cast<const float4*>(g_ds);
        float4 d = ds4[i];
        float4 v = w4[i];
        v.x = fmaf(d.x, inv, v.x);
        v.y = fmaf(d.y, inv, v.y);
        v.z = fmaf(d.z, inv, v.z);
        v.w = fmaf(d.w, inv, v.w);
        neww4[i] = v;
    }
}

// ---------------- launch ----------------
extern "C" void kernel_launch(void* const* d_in, const int* in_sizes, int n_in,
                              void* d_out, int out_size) {
    const float* x = (const float*)d_in[0];
    const float* w = (const float*)d_in[1];
    if (n_in >= 2 && in_sizes[0] == OUT_F * IN_F && in_sizes[1] == BATCH * IN_F) {
        w = (const float*)d_in[0];
        x = (const float*)d_in[1];
    }

    float* y_out = (float*)d_out;                       // [BATCH, OUT_F]
    float* w_out = y_out + (size_t)BATCH * OUT_F;       // [OUT_F, IN_F]

    __nv_bfloat16 *xhi, *xlo, *whi, *wlo;
    cudaGetSymbolAddress((void**)&xhi, g_xhi);
    cudaGetSymbolAddress((void**)&xlo, g_xlo);
    cudaGetSymbolAddress((void**)&whi, g_whi);
    cudaGetSymbolAddress((void**)&wlo, g_wlo);

    // 0) fused bf16 splits (+ nc/counter reset)
    {
        int n4x = BATCH * IN_F / 4;
        int n4t = n4x + OUT_F * IN_F / 4;
        split_bf16_fused<<<(n4t + 255) / 256, 256>>>(
            (const float4*)x, (const float4*)w,
            (uint2*)xhi, (uint2*)xlo, (uint2*)whi, (uint2*)wlo, n4x, n4t);
    }
    // 1) y = x @ W^T via bf16 mma.sync (round-12 config)
    {
        cudaFuncSetAttribute(gemm_bf16_kernel,
                             cudaFuncAttributeMaxDynamicSharedMemorySize, SMEM_GEMM);
        dim3 grid(OUT_F / BN_T, BATCH / BM_T);
        gemm_bf16_kernel<<<grid, 256, SMEM_GEMM>>>(xhi, xlo, whi, wlo, y_out);
    }
    // 2) top-2 per batch row + match counting
    top2_kernel<<<BATCH / 8, 256>>>(y_out);
    // 3) CSR build: scan + fill (separate kernels — fill spreads across SMs)
    scan_kernel<<<1, 1024>>>();
    fill_kernel<<<BATCH / 256, 256>>>();
    // 4) ds + global max (CSR-driven)
    update_kernel<<<OUT_F, 256>>>(x, w, y_out, OUT_F);
    // 5) finalize
    {
        int n4 = OUT_F * IN_F / 4;
        finalize_kernel<<<(n4 + 255) / 256, 256>>>((const float4*)w, (float4*)w_out, n4);
    }
}